// round 1
// baseline (speedup 1.0000x reference)
#include <cuda_runtime.h>
#include <cuda_bf16.h>
#include <cstdint>

// N = 2^22, 22 stages. Squared-magnitude domain, natural-order (no bitrev gather).
// Pass A: stages 1..11 (pairs in top-11 bits of p, i.e. low bits of q=brev22(p)).
// Pass B: stages 12..22 (pairs in low-11 bits of p), final sqrt + bit-reversed store.

#define NTOT (1 << 22)

__device__ float g_scratch[NTOT];

__device__ __forceinline__ float fsqrt_nr(float x) {
    // sqrt via rsqrt bit-hack + 2 Newton iterations (FMA pipe only).
    float y  = __int_as_float(0x5f3759df - (__float_as_int(x) >> 1));
    float hx = 0.5f * x;
    y = y * (1.5f - hx * y * y);
    y = y * (1.5f - hx * y * y);
    return x * y;   // x==0 -> 0 (y stays finite)
}

// sin(pi*u) for u in [-0.5, 0.5), degree-9 odd poly (abs err ~4e-6)
__device__ __forceinline__ float sinpi_poly(float u) {
    const float A1 =  3.14159265358979f;
    const float A3 = -5.16771278004997f;
    const float A5 =  2.55016403987735f;
    const float A7 = -0.599264529320792f;
    const float A9 =  0.0821458866111282f;
    float z = u * u;
    float w = fmaf(A9, z, A7);
    w = fmaf(w, z, A5);
    w = fmaf(w, z, A3);
    w = fmaf(w, z, A1);
    return u * w;
}

// Squared-domain butterfly: given Se,So (squares) and u = j/2^(s-1) - 0.5,
// c = cos(pi*f) = -sin(pi*u);  out+/- = Se+So +/- 2*c*sqrt(Se*So)
__device__ __forceinline__ void butterfly_sq(float Se, float So, float u,
                                             float& op, float& om) {
    float r  = fsqrt_nr(Se * So);
    float sv = sinpi_poly(u);       // = -c
    float T  = r * sv;
    float Sp = Se + So;
    op = fmaf(-2.0f, T, Sp);        // Sp + 2*c*r
    om = fmaf( 2.0f, T, Sp);        // Sp - 2*c*r
    op = fmaxf(op, 0.0f);
    om = fmaxf(om, 0.0f);
}

// ---------------- Pass A: stages 1..11 ----------------
// Tile: all 2048 "rtop" values (rtop = brev11(p>>11)) x 4 low indices.
// In rtop coordinates stage s pairs bit (s-1) and twiddle j = rtopE & (2^(s-1)-1).
// smem row stride 5 (pad) to reduce bank conflicts.
__global__ void __launch_bounds__(256) fftA_kernel(const float* __restrict__ x) {
    __shared__ float tile[2048 * 5];   // 40 KB
    const int t  = threadIdx.x;
    const int lb = blockIdx.x << 2;    // 4 low indices per block, 512 blocks

    // Load (gather: 32B fully-used sectors per rtop)
    #pragma unroll 4
    for (int e = t; e < 8192; e += 256) {
        int rtop = e >> 2, li = e & 3;
        int p = ((int)(__brev((unsigned)rtop) >> 21) << 11) + lb + li;
        tile[rtop * 5 + li] = x[p];
    }
    __syncthreads();

    // Stage 1: c = 1, signed raw inputs -> squares
    #pragma unroll 4
    for (int bid = t; bid < 4096; bid += 256) {
        int brt = bid >> 2, li = bid & 3;
        int iE = ((brt << 1)) * 5 + li;
        int iO = iE + 5;
        float e = tile[iE], o = tile[iO];
        float s0 = e + o, d0 = e - o;
        tile[iE] = s0 * s0;
        tile[iO] = d0 * d0;
    }
    __syncthreads();

    // Stages 2..11 on squares
    #pragma unroll
    for (int s = 2; s <= 11; ++s) {
        const int   b      = s - 1;
        const int   mask   = (1 << b) - 1;
        const float fscale = 1.0f / (float)(1 << b);
        #pragma unroll 2
        for (int bid = t; bid < 4096; bid += 256) {
            int brt = bid >> 2, li = bid & 3;
            int rE = ((brt >> b) << (b + 1)) | (brt & mask);
            int iE = rE * 5 + li;
            int iO = iE + 5 * (1 << b);
            float Se = tile[iE], So = tile[iO];
            int j = rE & mask;
            float u = fmaf((float)j, fscale, -0.5f);
            float op, om;
            butterfly_sq(Se, So, u, op, om);
            tile[iE] = op;
            tile[iO] = om;
        }
        __syncthreads();
    }

    // Store to scratch in pass-B-friendly layout:
    // saddr = (rtop>>2)*8192 + l*4 + (rtop&3)  -> 128B coalesced segments
    #pragma unroll 4
    for (int e = t; e < 8192; e += 256) {
        int rlow = e & 3, li = (e >> 2) & 3, G = e >> 4;
        int rtop = (G << 2) | rlow;
        g_scratch[(G << 13) + ((lb + li) << 2) + rlow] = tile[rtop * 5 + li];
    }
}

// ---------------- Pass B: stages 12..22 + final sqrt ----------------
// Block g handles rB in [4g, 4g+4) and all 2048 low-11 indices l.
// q = brev11(l)*2048 + rB ; stage s pairs l bit b=22-s ; j = q & (2^(s-1)-1).
__global__ void __launch_bounds__(256) fftB_kernel(float* __restrict__ out) {
    __shared__ float val[8192];   // 32 KB, layout idx = l*4 + rb
    const int t  = threadIdx.x;
    const int g  = blockIdx.x;    // 512 blocks
    const int R0 = g << 2;

    // Contiguous coalesced load from scratch
    const float* __restrict__ src = g_scratch + ((long)g << 13);
    #pragma unroll 4
    for (int e = t; e < 8192; e += 256) val[e] = src[e];
    __syncthreads();

    #pragma unroll
    for (int s = 12; s <= 22; ++s) {
        const int   b      = 22 - s;             // 10 .. 0
        const int   mask   = (1 << (21 - b)) - 1;
        const float fscale = 1.0f / (float)(1 << (21 - b));
        #pragma unroll 2
        for (int bid = t; bid < 4096; bid += 256) {
            int rb  = bid & 3, blt = bid >> 2;
            int lE  = ((blt >> b) << (b + 1)) | (blt & ((1 << b) - 1));
            int iE  = (lE << 2) + rb;
            int iO  = iE + (4 << b);
            float Se = val[iE], So = val[iO];
            int rl = (int)(__brev((unsigned)lE) >> 21);
            int j  = ((rl << 11) | (R0 + rb)) & mask;
            float u = fmaf((float)j, fscale, -0.5f);
            float op, om;
            butterfly_sq(Se, So, u, op, om);
            val[iE] = op;
            val[iO] = om;
        }
        __syncthreads();
    }

    // Final sqrt + bit-reversed scatter (32B segments: 4 consecutive rB per l)
    #pragma unroll 4
    for (int e = t; e < 8192; e += 256) {
        int rb = e & 3, l = e >> 2;
        int q  = ((int)(__brev((unsigned)l) >> 21) << 11) + R0 + rb;
        out[q] = fsqrt_nr(val[e]);
    }
}

extern "C" void kernel_launch(void* const* d_in, const int* in_sizes, int n_in,
                              void* d_out, int out_size) {
    const float* x = (const float*)d_in[0];
    float* out = (float*)d_out;
    fftA_kernel<<<512, 256>>>(x);
    fftB_kernel<<<512, 256>>>(out);
}

// round 3
// speedup vs baseline: 3.0178x; 3.0178x over previous
#include <cuda_runtime.h>
#include <cstdint>

#define PI  3.14159265358979323846f
#define PIH 1.57079632679489662f

// 16 MB scratch between passes (float4 lanes = rB group of 4)
__device__ float4 g_scr[1 << 20];

__device__ __forceinline__ float sin_ap(float x){ float y; asm("sin.approx.f32 %0, %1;" : "=f"(y) : "f"(x)); return y; }
__device__ __forceinline__ float sqrt_ap(float x){ float y; asm("sqrt.approx.f32 %0, %1;" : "=f"(y) : "f"(x)); return y; }
__device__ __forceinline__ int   swz(int r){ return r ^ ((r >> 2) & 7); }

// squared-magnitude-domain butterfly: Se,So >= 0, c = cos(angle)
__device__ __forceinline__ void bfly(float& Se, float& So, float c){
    float r  = sqrt_ap(Se * So);
    float T  = c * r;
    float Sp = Se + So;
    Se = fmaxf(fmaf( 2.f, T, Sp), 0.f);
    So = fmaxf(fmaf(-2.f, T, Sp), 0.f);
}

__device__ __forceinline__ float4 sqrt4(float4 v){
    v.x = sqrt_ap(v.x); v.y = sqrt_ap(v.y); v.z = sqrt_ap(v.z); v.w = sqrt_ap(v.w);
    return v;
}

// ---------- Pass A grouped round: stages (B+1, B+2), pairing bits B (lower) then B+1 ----------
template<int B>
__device__ __forceinline__ void roundA(float4* tile, int t){
    const float hs = PI / (float)(2 << B);    // h = pi*j / 2^(B+1)
    #pragma unroll
    for (int gb = t; gb < 512; gb += 256){
        int base = ((gb >> B) << (B + 2)) | (gb & ((1 << B) - 1));
        int i00 = swz(base);
        int i10 = swz(base + (1 << B));       // stage-s partner (bit B)
        int i01 = swz(base + (2 << B));       // stage-(s+1) partner (bit B+1)
        int i11 = swz(base + 3 * (1 << B));
        float h  = (float)(gb & ((1 << B) - 1)) * hs;
        float sh = sin_ap(h), ch = sin_ap(PIH - h);
        float c2 = fmaf(-2.f * sh, sh, 1.f);
        float msh = -sh;
        float4 v00 = tile[i00], v10 = tile[i10], v01 = tile[i01], v11 = tile[i11];
#define RL(L) { bfly(v00.L, v10.L, c2); bfly(v01.L, v11.L, c2); \
                bfly(v00.L, v01.L, ch); bfly(v10.L, v11.L, msh); }
        RL(x) RL(y) RL(z) RL(w)
#undef RL
        tile[i00] = v00; tile[i10] = v10; tile[i01] = v01; tile[i11] = v11;
    }
}

// ---------- Pass B grouped round: stages (21-B, 22-B), pairing bits B+1 (upper) then B ----------
template<int B>
__device__ __forceinline__ void roundB(float4* tile, int t, int R0){
    const int   S  = 21 - B;                  // first stage of the pair
    const float hs = PI / (float)(1 << S);    // h = pi*j / 2^S
    #pragma unroll
    for (int gb = t; gb < 512; gb += 256){
        int base = ((gb >> B) << (B + 2)) | (gb & ((1 << B) - 1));
        int i00 = swz(base);
        int i01 = swz(base + (1 << B));       // stage-(s+1) partner (bit B)
        int i10 = swz(base + (2 << B));       // stage-s partner (bit B+1)
        int i11 = swz(base + 3 * (1 << B));
        int rl = (int)(__brev((unsigned)base) >> 21);
        int jb = ((rl & ((1 << (S - 12)) - 1)) << 11) + R0;
        float h0 = (float)jb * hs;
        float4 v00 = tile[i00], v01 = tile[i01], v10 = tile[i10], v11 = tile[i11];
#define RLB(L, K) { float h = fmaf((float)K, hs, h0); \
        float sh = sin_ap(h), ch = sin_ap(PIH - h); \
        float c2 = fmaf(-2.f * sh, sh, 1.f); float msh = -sh; \
        bfly(v00.L, v10.L, c2); bfly(v01.L, v11.L, c2); \
        bfly(v00.L, v01.L, ch); bfly(v10.L, v11.L, msh); }
        RLB(x,0) RLB(y,1) RLB(z,2) RLB(w,3)
#undef RLB
        tile[i00] = v00; tile[i01] = v01; tile[i10] = v10; tile[i11] = v11;
    }
}

// ================= Pass A: stages 1..11 (rtop space, ascending bits) =================
__global__ void __launch_bounds__(256) fftA(const float4* __restrict__ x4){
    __shared__ float4 tile[2048];             // 32 KB, lanes = 4 consecutive low indices
    const int t   = threadIdx.x;
    const int lb4 = blockIdx.x;               // low-index group: l = 4*lb4 + lane

    #pragma unroll
    for (int r = t; r < 2048; r += 256){
        int T = (int)(__brev((unsigned)r) >> 21);     // brev11
        tile[swz(r)] = x4[(T << 9) + lb4];
    }
    __syncthreads();

    // stages (1,2): closed form, no transcendentals
    #pragma unroll
    for (int gb = t; gb < 512; gb += 256){
        int b = gb << 2;
        int i0 = swz(b), i1 = swz(b + 1), i2 = swz(b + 2), i3 = swz(b + 3);
        float4 e0 = tile[i0], e1 = tile[i1], e2 = tile[i2], e3 = tile[i3];
        float4 w0, w1, w2;
#define G12(L) { \
        float A  = fabsf(e0.L + e1.L), Bv = fabsf(e2.L + e3.L); \
        float d1 = e0.L - e1.L,        d2 = e2.L - e3.L;        \
        float s  = A + Bv,             q  = A - Bv;             \
        w0.L = s * s; w2.L = q * q; w1.L = fmaf(d1, d1, d2 * d2); }
        G12(x) G12(y) G12(z) G12(w)
#undef G12
        tile[i0] = w0; tile[i1] = w1; tile[i2] = w2; tile[i3] = w1;
    }
    __syncthreads();

    roundA<2>(tile, t); __syncthreads();
    roundA<4>(tile, t); __syncthreads();
    roundA<6>(tile, t); __syncthreads();
    roundA<8>(tile, t); __syncthreads();

    // single stage 11 (pairs bit 10)
    #pragma unroll
    for (int bl = t; bl < 1024; bl += 256){
        float c = sin_ap(PIH - (float)bl * (PI / 1024.f));
        int ia = swz(bl), ib = swz(bl + 1024);
        float4 a = tile[ia], b = tile[ib];
        bfly(a.x, b.x, c); bfly(a.y, b.y, c); bfly(a.z, b.z, c); bfly(a.w, b.w, c);
        tile[ia] = a; tile[ib] = b;
    }
    __syncthreads();

    // transpose-store to scratch (pass-B layout: float4 lanes = rB group)
    const float* ts  = (const float*)tile;
    float*       scr = (float*)g_scr;
    #pragma unroll
    for (int e = t; e < 8192; e += 256){
        int r0 = e & 3, li = (e >> 2) & 3, G = e >> 4;
        int r  = (G << 2) | r0;
        scr[(G << 13) + (((lb4 << 2) + li) << 2) + r0] = ts[swz(r) * 4 + li];
    }
}

// ================= Pass B: stages 12..22 + final sqrt + bit-reversed store =================
__global__ void __launch_bounds__(256) fftB(float4* __restrict__ out4){
    __shared__ float4 tile[2048];             // lanes = rB = 4g + k
    const int t  = threadIdx.x;
    const int g  = blockIdx.x;
    const int R0 = g << 2;

    #pragma unroll
    for (int l = t; l < 2048; l += 256)
        tile[swz(l)] = g_scr[(g << 11) + l];
    __syncthreads();

    // single stage 12 (pairs bit 10): twiddle depends only on lane -> hoisted
    {
        float ca = sin_ap(PIH - (float)(R0 + 0) * (PI / 2048.f));
        float cb = sin_ap(PIH - (float)(R0 + 1) * (PI / 2048.f));
        float cc = sin_ap(PIH - (float)(R0 + 2) * (PI / 2048.f));
        float cd = sin_ap(PIH - (float)(R0 + 3) * (PI / 2048.f));
        #pragma unroll
        for (int bl = t; bl < 1024; bl += 256){
            int ia = swz(bl), ib = swz(bl + 1024);
            float4 a = tile[ia], b = tile[ib];
            bfly(a.x, b.x, ca); bfly(a.y, b.y, cb); bfly(a.z, b.z, cc); bfly(a.w, b.w, cd);
            tile[ia] = a; tile[ib] = b;
        }
    }
    __syncthreads();

    roundB<8>(tile, t, R0); __syncthreads();
    roundB<6>(tile, t, R0); __syncthreads();
    roundB<4>(tile, t, R0); __syncthreads();
    roundB<2>(tile, t, R0); __syncthreads();

    // final round: stages (21,22) fused with sqrt + bit-reversed output
    {
        const float hs = PI / (float)(1 << 21);
        #pragma unroll
        for (int gb = t; gb < 512; gb += 256){
            int base = gb << 2;
            int i00 = swz(base), i01 = swz(base + 1), i10 = swz(base + 2), i11 = swz(base + 3);
            int rl = (int)(__brev((unsigned)base) >> 21);
            int jb = ((rl & 511) << 11) + R0;
            float h0 = (float)jb * hs;
            float4 v00 = tile[i00], v01 = tile[i01], v10 = tile[i10], v11 = tile[i11];
#define RLF(L, K) { float h = fmaf((float)K, hs, h0); \
            float sh = sin_ap(h), ch = sin_ap(PIH - h); \
            float c2 = fmaf(-2.f * sh, sh, 1.f); float msh = -sh; \
            bfly(v00.L, v10.L, c2); bfly(v01.L, v11.L, c2); \
            bfly(v00.L, v01.L, ch); bfly(v10.L, v11.L, msh); }
            RLF(x,0) RLF(y,1) RLF(z,2) RLF(w,3)
#undef RLF
            out4[(((int)(__brev((unsigned)(base + 0)) >> 21)) << 9) + g] = sqrt4(v00);
            out4[(((int)(__brev((unsigned)(base + 1)) >> 21)) << 9) + g] = sqrt4(v01);
            out4[(((int)(__brev((unsigned)(base + 2)) >> 21)) << 9) + g] = sqrt4(v10);
            out4[(((int)(__brev((unsigned)(base + 3)) >> 21)) << 9) + g] = sqrt4(v11);
        }
    }
}

extern "C" void kernel_launch(void* const* d_in, const int* in_sizes, int n_in,
                              void* d_out, int out_size) {
    const float4* x4 = (const float4*)d_in[0];
    fftA<<<512, 256>>>(x4);
    fftB<<<512, 256>>>((float4*)d_out);
}